// round 6
// baseline (speedup 1.0000x reference)
#include <cuda_runtime.h>
#include <cuda_fp16.h>
#include <cstdint>

#define NN 100000
#define EE 1600000
#define HH 128
#define GG 256
#define CC 16
#define KK 2

#define SCAN_BLOCKS ((NN + 255) / 256)   // 391
#define AGG_BLOCKS 1024

// ---------------- device scratch (static, allowed) ----------------
__device__ __half g_xs16[(size_t)NN * HH]; // dis-scaled transformed features (fp16)
__device__ __half g_h16 [(size_t)NN * HH]; // layer activations (fp16)
__device__ float g_dis[NN];
__device__ int   g_deg[NN];
__device__ int   g_rowptr[NN + 1];
__device__ int   g_cursor[NN];
__device__ int   g_csrc[EE];
__device__ float g_stats[2 * HH];          // [0..127] sum, [128..255] sumsq
__device__ float g_bns[HH];                // BN affine scale
__device__ float g_bnt[HH];                // BN affine shift
__device__ float g_pool[GG * HH];
__device__ float g_cnt[GG];
__device__ int   g_i64;                    // 1 if index tensors are int64
__device__ int   g_blk[SCAN_BLOCKS + 8];
__device__ int   g_blkoff[SCAN_BLOCKS + 8];
__device__ __half g_wh[HH * HH];           // W'^T hi fp16, layout [n][k]
__device__ __half g_wl[HH * HH];           // W'^T lo fp16 (residual)
__device__ float g_wr[HH];                 // r[n] = sum_k t[k] * W[k][n]
__device__ unsigned g_arr;                 // arrival counter

__device__ __forceinline__ long long idx_at(const void* p, long long i) {
    if (g_i64) return ((const long long*)p)[i];
    return (long long)((const int*)p)[i];
}

__device__ __forceinline__ void mma_f16(float* c, const uint32_t* a,
                                        uint32_t b0, uint32_t b1) {
    asm volatile(
        "mma.sync.aligned.m16n8k16.row.col.f32.f16.f16.f32 "
        "{%0,%1,%2,%3}, {%4,%5,%6,%7}, {%8,%9}, {%0,%1,%2,%3};\n"
        : "+f"(c[0]), "+f"(c[1]), "+f"(c[2]), "+f"(c[3])
        : "r"(a[0]), "r"(a[1]), "r"(a[2]), "r"(a[3]), "r"(b0), "r"(b1));
}

__device__ __forceinline__ uint32_t pack2(float a, float b) {
    __half2 h = __floats2half2_rn(a, b);
    return *(uint32_t*)&h;
}

// ---------------- init (+ index width detection in block 0) ----------------
__global__ void k_init(const int* ei) {
    int i = blockIdx.x * 256 + threadIdx.x;
    if (blockIdx.x == 0 && threadIdx.x < 32) {
        int lane = threadIdx.x;
        int v = ei[2 * lane + 1] | ei[2 * (lane + 32) + 1] |
                ei[2 * (lane + 64) + 1] | ei[2 * (lane + 96) + 1];
        unsigned m = __ballot_sync(0xffffffffu, v != 0);
        if (lane == 0) g_i64 = (m == 0) ? 1 : 0;
    }
    if (i < NN) g_deg[i] = 0;
    if (i < GG * HH) g_pool[i] = 0.f;
    if (i < GG) g_cnt[i] = 0.f;
    if (i < 2 * HH) g_stats[i] = 0.f;
    if (i == 0) g_arr = 0u;
}

// ---------------- CSR build ----------------
__global__ void k_hist(const void* ei) {
    int e = blockIdx.x * 256 + threadIdx.x;
    if (e < EE) {
        int d = (int)idx_at(ei, (long long)EE + e);
        atomicAdd(&g_deg[d], 1);
    }
}

// pass 1 (+ merged pass 2 in last block): per-block sums, then scan of block sums
__global__ void k_scan1() {
    int tid = threadIdx.x;
    int i = blockIdx.x * 256 + tid;
    int v = (i < NN) ? g_deg[i] : 0;
#pragma unroll
    for (int o = 16; o; o >>= 1) v += __shfl_down_sync(0xffffffffu, v, o);
    __shared__ int ws[8];
    if ((tid & 31) == 0) ws[tid >> 5] = v;
    __syncthreads();
    if (tid < 8) {
        int s = ws[tid];
#pragma unroll
        for (int o = 4; o; o >>= 1) s += __shfl_down_sync(0xffu, s, o);
        if (tid == 0) g_blk[blockIdx.x] = s;
    }
    __threadfence();
    __syncthreads();
    __shared__ int isLast;
    if (tid == 0)
        isLast = (atomicAdd(&g_arr, 1u) == (unsigned)(gridDim.x - 1)) ? 1 : 0;
    __syncthreads();
    if (isLast) {
        __shared__ int s[256];
        int i0 = 2 * tid, i1 = 2 * tid + 1;
        int v0 = (i0 < SCAN_BLOCKS) ? g_blk[i0] : 0;
        int v1 = (i1 < SCAN_BLOCKS) ? g_blk[i1] : 0;
        int p = v0 + v1;
        s[tid] = p;
        __syncthreads();
        for (int d = 1; d < 256; d <<= 1) {
            int x = (tid >= d) ? s[tid - d] : 0;
            __syncthreads();
            s[tid] += x;
            __syncthreads();
        }
        int excl = s[tid] - p;
        if (i0 < SCAN_BLOCKS) g_blkoff[i0] = excl;
        if (i1 < SCAN_BLOCKS) g_blkoff[i1] = excl + v0;
        if (tid == 255) g_rowptr[NN] = s[255];
        if (tid == 0) g_arr = 0u;
    }
}

// pass 3: local scan + block offset -> rowptr/cursor; also dis + graph node counts
__global__ void k_scan3(const void* batch) {
    int tid = threadIdx.x;
    int i = blockIdx.x * 256 + tid;
    int v = (i < NN) ? g_deg[i] : 0;
    int x = v;
#pragma unroll
    for (int o = 1; o < 32; o <<= 1) {
        int y = __shfl_up_sync(0xffffffffu, x, o);
        if ((tid & 31) >= o) x += y;
    }
    __shared__ int ws[8];
    if ((tid & 31) == 31) ws[tid >> 5] = x;
    __syncthreads();
    if (tid < 8) {
        int s = ws[tid];
#pragma unroll
        for (int o = 1; o < 8; o <<= 1) {
            int y = __shfl_up_sync(0xffu, s, o);
            if (tid >= o) s += y;
        }
        ws[tid] = s;
    }
    __syncthreads();
    int warpoff = (tid >= 32) ? ws[(tid >> 5) - 1] : 0;
    int excl = x - v + warpoff + g_blkoff[blockIdx.x];
    if (i < NN) {
        g_rowptr[i] = excl;
        g_cursor[i] = excl;
        g_dis[i] = rsqrtf((float)v + 1.0f);
        int g = (int)idx_at(batch, i);
        atomicAdd(&g_cnt[g], 1.0f);
    }
}

__global__ void k_place(const void* ei) {
    int e = blockIdx.x * 256 + threadIdx.x;
    if (e < EE) {
        int d = (int)idx_at(ei, (long long)EE + e);
        int pos = atomicAdd(&g_cursor[d], 1);
        g_csrc[pos] = (int)idx_at(ei, (long long)e);
    }
}

// ---------------- W prep: double-fp16 split, transposed [n][k] ----------------
__global__ void k_prepw1(const float* __restrict__ W) {
    int idx = blockIdx.x * 256 + threadIdx.x;
    if (idx < HH * HH) {
        int k = idx >> 7, n = idx & 127;
        float v = W[idx];
        __half h = __float2half_rn(v);
        g_wh[n * HH + k] = h;
        g_wl[n * HH + k] = __float2half_rn(v - __half2float(h));
    }
    if (blockIdx.x == 0 && threadIdx.x < HH) g_wr[threadIdx.x] = 0.f;
}

// layers 2/3: fold BN scale into W rows + compute r; grid = 65 blocks
__global__ void k_prepw_aff_r(const float* __restrict__ W) {
    if (blockIdx.x < 64) {
        int idx = blockIdx.x * 256 + threadIdx.x;
        int k = idx >> 7, n = idx & 127;
        float v = W[idx] * g_bns[k];
        __half h = __float2half_rn(v);
        g_wh[n * HH + k] = h;
        g_wl[n * HH + k] = __float2half_rn(v - __half2float(h));
    } else if (threadIdx.x < HH) {
        int n = threadIdx.x;
        float r = 0.f;
#pragma unroll 4
        for (int k = 0; k < HH; k++) r = fmaf(g_bnt[k], W[k * HH + n], r);
        g_wr[n] = r;
    }
}

// ---------------- fp16 tensor-core GEMM: xs16 = dis * (A @ W' + r) ----------------
// MODE 0: A fp32 -> hi/lo fp16 split, 3 passes (Ah*Wh + Ah*Wl + Al*Wh)
// MODE 1: A fp16 (exact), 2 passes (Ah*Wh + Ah*Wl)
// smem: uint32 tiles with row stride 20 (bank-conflict-free fragment loads)
#define ST 20
#define SA_H 0
#define SA_L (128 * ST)
#define SW_H (2 * 128 * ST)
#define SW_L (3 * 128 * ST)
#define SMEM_U32 (4 * 128 * ST)

template<int MODE>
__global__ void __launch_bounds__(256, 2) k_gemm_tc(const float* __restrict__ Ain) {
    extern __shared__ uint32_t sm[];
    int tid = threadIdx.x;
    int wid = tid >> 5, lane = tid & 31;
    int wm = wid >> 1, wn = wid & 1;        // 4 x 2 warp grid
    int ly = lane >> 2, lx = lane & 3;
    int rbase = blockIdx.x * 128;

    float acc[2][8][4];
#pragma unroll
    for (int mt = 0; mt < 2; mt++)
#pragma unroll
        for (int j = 0; j < 8; j++)
#pragma unroll
            for (int q = 0; q < 4; q++) acc[mt][j][q] = 0.f;

    for (int ch = 0; ch < 4; ch++) {
        int kbase = ch * 32;
        // A chunk: 128 rows x 32 halves = 128 x 4 uint4 slots = 512 slots
#pragma unroll
        for (int i = 0; i < 2; i++) {
            int idx = i * 256 + tid;
            int m = idx >> 2, q = idx & 3;
            int gr = rbase + m;
            if (MODE == 0) {
                float4 v0 = make_float4(0.f, 0.f, 0.f, 0.f);
                float4 v1 = make_float4(0.f, 0.f, 0.f, 0.f);
                if (gr < NN) {
                    v0 = *(const float4*)&Ain[(size_t)gr * HH + kbase + 8 * q];
                    v1 = *(const float4*)&Ain[(size_t)gr * HH + kbase + 8 * q + 4];
                }
                __half h0 = __float2half_rn(v0.x), h1 = __float2half_rn(v0.y);
                __half h2 = __float2half_rn(v0.z), h3 = __float2half_rn(v0.w);
                __half h4 = __float2half_rn(v1.x), h5 = __float2half_rn(v1.y);
                __half h6 = __float2half_rn(v1.z), h7 = __float2half_rn(v1.w);
                uint4 hi = make_uint4(
                    pack2(__half2float(h0), __half2float(h1)),
                    pack2(__half2float(h2), __half2float(h3)),
                    pack2(__half2float(h4), __half2float(h5)),
                    pack2(__half2float(h6), __half2float(h7)));
                // note: pack2 re-rounds the already-fp16 values (exact)
                uint4 lo = make_uint4(
                    pack2(v0.x - __half2float(h0), v0.y - __half2float(h1)),
                    pack2(v0.z - __half2float(h2), v0.w - __half2float(h3)),
                    pack2(v1.x - __half2float(h4), v1.y - __half2float(h5)),
                    pack2(v1.z - __half2float(h6), v1.w - __half2float(h7)));
                *(uint4*)&sm[SA_H + m * ST + 4 * q] = hi;
                *(uint4*)&sm[SA_L + m * ST + 4 * q] = lo;
            } else {
                uint4 u = make_uint4(0u, 0u, 0u, 0u);
                if (gr < NN)
                    u = *(const uint4*)&g_h16[(size_t)gr * HH + kbase + 8 * q];
                *(uint4*)&sm[SA_H + m * ST + 4 * q] = u;
            }
        }
        // W chunk: 128 n-rows x 32 halves (hi and lo)
#pragma unroll
        for (int i = 0; i < 2; i++) {
            int idx = i * 256 + tid;
            int n = idx >> 2, q = idx & 3;
            *(uint4*)&sm[SW_H + n * ST + 4 * q] =
                *(const uint4*)&g_wh[n * HH + kbase + 8 * q];
            *(uint4*)&sm[SW_L + n * ST + 4 * q] =
                *(const uint4*)&g_wl[n * HH + kbase + 8 * q];
        }
        __syncthreads();

#pragma unroll
        for (int ks = 0; ks < 2; ks++) {            // two k16 steps per chunk
            int koff = ks * 8;                       // uint32 offset (16 halves)
            uint32_t ah[2][4], al[2][4];
#pragma unroll
            for (int mt = 0; mt < 2; mt++) {
                int base = (wm * 32 + mt * 16 + ly) * ST + koff + lx;
                ah[mt][0] = sm[SA_H + base];
                ah[mt][1] = sm[SA_H + base + 8 * ST];
                ah[mt][2] = sm[SA_H + base + 4];
                ah[mt][3] = sm[SA_H + base + 8 * ST + 4];
                if (MODE == 0) {
                    al[mt][0] = sm[SA_L + base];
                    al[mt][1] = sm[SA_L + base + 8 * ST];
                    al[mt][2] = sm[SA_L + base + 4];
                    al[mt][3] = sm[SA_L + base + 8 * ST + 4];
                }
            }
#pragma unroll
            for (int j = 0; j < 8; j++) {
                int bbase = (wn * 64 + 8 * j + ly) * ST + koff + lx;
                uint32_t bh0 = sm[SW_H + bbase];
                uint32_t bh1 = sm[SW_H + bbase + 4];
                uint32_t bl0 = sm[SW_L + bbase];
                uint32_t bl1 = sm[SW_L + bbase + 4];
#pragma unroll
                for (int mt = 0; mt < 2; mt++) {
                    mma_f16(acc[mt][j], ah[mt], bh0, bh1);
                    mma_f16(acc[mt][j], ah[mt], bl0, bl1);
                    if (MODE == 0) mma_f16(acc[mt][j], al[mt], bh0, bh1);
                }
            }
        }
        __syncthreads();
    }

    // epilogue: xs16 = dis[r] * (acc + wr)
#pragma unroll
    for (int mt = 0; mt < 2; mt++) {
        int r0 = rbase + wm * 32 + mt * 16 + ly;
        int r1 = r0 + 8;
        float d0 = (r0 < NN) ? g_dis[r0] : 0.f;
        float d1 = (r1 < NN) ? g_dis[r1] : 0.f;
#pragma unroll
        for (int j = 0; j < 8; j++) {
            int cb = wn * 64 + 8 * j + 2 * lx;
            float ra = g_wr[cb], rb = g_wr[cb + 1];
            if (r0 < NN) {
                __half2 o = __floats2half2_rn(d0 * (acc[mt][j][0] + ra),
                                              d0 * (acc[mt][j][1] + rb));
                *(__half2*)&g_xs16[(size_t)r0 * HH + cb] = o;
            }
            if (r1 < NN) {
                __half2 o = __floats2half2_rn(d1 * (acc[mt][j][2] + ra),
                                              d1 * (acc[mt][j][3] + rb));
                *(__half2*)&g_xs16[(size_t)r1 * HH + cb] = o;
            }
        }
    }
}

// ------- aggregation + relu + BN stats (+ pooling on last layer) + BN solve -------
#define ACCS(u0, u1, X, Y, Z, W) { \
    float2 t0 = __half22float2(*(__half2*)&(u0)); \
    float2 t1 = __half22float2(*(__half2*)&(u1)); \
    X += t0.x; Y += t0.y; Z += t1.x; W += t1.y; }

template<bool LAST>
__global__ void __launch_bounds__(256) k_agg(const float* __restrict__ bias,
                                             const void* __restrict__ batch,
                                             const float* __restrict__ gamma,
                                             const float* __restrict__ beta) {
    int tid = threadIdx.x;
    int wid = tid >> 5, lane = tid & 31;
    float4 b4 = ((const float4*)bias)[lane];
    float s0 = 0.f, s1 = 0.f, s2 = 0.f, s3 = 0.f;
    float q0 = 0.f, q1 = 0.f, q2 = 0.f, q3 = 0.f;
    const uint2* xsv = (const uint2*)g_xs16;

    for (long long i = (long long)blockIdx.x * 8 + wid; i < NN;
         i += (long long)AGG_BLOCKS * 8) {
        uint2 u = xsv[i * 32 + lane];                 // self term
        float ax0, ay0, az0, aw0;
        float ax1 = 0.f, ay1 = 0.f, az1 = 0.f, aw1 = 0.f;
        {
            float2 a0 = __half22float2(*(__half2*)&u.x);
            float2 a1 = __half22float2(*(__half2*)&u.y);
            ax0 = a0.x; ay0 = a0.y; az0 = a1.x; aw0 = a1.y;
        }
        int e0 = g_rowptr[i], e1 = g_rowptr[i + 1];
        int e = e0;
        for (; e + 4 <= e1; e += 4) {
            int sA = g_csrc[e], sB = g_csrc[e + 1];
            int sC = g_csrc[e + 2], sD = g_csrc[e + 3];
            uint2 vA = xsv[(long long)sA * 32 + lane];
            uint2 vB = xsv[(long long)sB * 32 + lane];
            uint2 vC = xsv[(long long)sC * 32 + lane];
            uint2 vD = xsv[(long long)sD * 32 + lane];
            ACCS(vA.x, vA.y, ax0, ay0, az0, aw0);
            ACCS(vB.x, vB.y, ax1, ay1, az1, aw1);
            ACCS(vC.x, vC.y, ax0, ay0, az0, aw0);
            ACCS(vD.x, vD.y, ax1, ay1, az1, aw1);
        }
        for (; e < e1; e++) {
            int s = g_csrc[e];
            uint2 v = xsv[(long long)s * 32 + lane];
            ACCS(v.x, v.y, ax0, ay0, az0, aw0);
        }
        float acx = ax0 + ax1, acy = ay0 + ay1;
        float acz = az0 + az1, acw = aw0 + aw1;
        float d = g_dis[i];
        float yx = fmaxf(fmaf(d, acx, b4.x), 0.f);
        float yy = fmaxf(fmaf(d, acy, b4.y), 0.f);
        float yz = fmaxf(fmaf(d, acz, b4.z), 0.f);
        float yw = fmaxf(fmaf(d, acw, b4.w), 0.f);
        if (!LAST) {
            uint2 o;
            *(__half2*)&o.x = __floats2half2_rn(yx, yy);
            *(__half2*)&o.y = __floats2half2_rn(yz, yw);
            ((uint2*)g_h16)[i * 32 + lane] = o;
        } else {
            int g = (int)idx_at(batch, i);
            float* p = &g_pool[g * HH + lane * 4];
            atomicAdd(p + 0, yx);
            atomicAdd(p + 1, yy);
            atomicAdd(p + 2, yz);
            atomicAdd(p + 3, yw);
        }
        s0 += yx; s1 += yy; s2 += yz; s3 += yw;
        q0 += yx * yx; q1 += yy * yy; q2 += yz * yz; q3 += yw * yw;
    }
    __shared__ float red[2 * HH];
    red[tid] = 0.f;
    __syncthreads();
    atomicAdd(&red[lane * 4 + 0], s0);
    atomicAdd(&red[lane * 4 + 1], s1);
    atomicAdd(&red[lane * 4 + 2], s2);
    atomicAdd(&red[lane * 4 + 3], s3);
    atomicAdd(&red[HH + lane * 4 + 0], q0);
    atomicAdd(&red[HH + lane * 4 + 1], q1);
    atomicAdd(&red[HH + lane * 4 + 2], q2);
    atomicAdd(&red[HH + lane * 4 + 3], q3);
    __syncthreads();
    atomicAdd(&g_stats[tid], red[tid]);
    // last-block epilogue: BN stats -> affine
    __threadfence();
    __syncthreads();
    __shared__ int isLast;
    if (tid == 0)
        isLast = (atomicAdd(&g_arr, 1u) == (unsigned)(AGG_BLOCKS - 1)) ? 1 : 0;
    __syncthreads();
    if (isLast) {
        if (tid < HH) {
            float m = g_stats[tid] * (1.0f / NN);
            float v = g_stats[HH + tid] * (1.0f / NN) - m * m;
            v = fmaxf(v, 0.f);
            float s = gamma[tid] * rsqrtf(v + 1e-5f);
            g_bns[tid] = s;
            g_bnt[tid] = beta[tid] - m * s;
            g_stats[tid] = 0.f;
            g_stats[HH + tid] = 0.f;
        }
        if (tid == 0) g_arr = 0u;
    }
}

// ---------------- final head: pooled(BN3) ++ clinical -> linear ----------------
__global__ void k_final(const float* __restrict__ clinical,
                        const float* __restrict__ Wc,
                        const float* __restrict__ bc,
                        float* __restrict__ out) {
    int g = blockIdx.x, j = threadIdx.x;   // 128 threads
    float cnt = fmaxf(g_cnt[g], 1.0f);
    float p = g_pool[g * HH + j] / cnt;
    p = fmaf(p, g_bns[j], g_bnt[j]);
    float r0 = p * Wc[j * KK + 0];
    float r1 = p * Wc[j * KK + 1];
    if (j < CC) {
        float cl = clinical[g * CC + j];
        r0 = fmaf(cl, Wc[(HH + j) * KK + 0], r0);
        r1 = fmaf(cl, Wc[(HH + j) * KK + 1], r1);
    }
    __shared__ float sm0[128], sm1[128];
    sm0[j] = r0; sm1[j] = r1;
    __syncthreads();
    for (int d = 64; d > 0; d >>= 1) {
        if (j < d) { sm0[j] += sm0[j + d]; sm1[j] += sm1[j + d]; }
        __syncthreads();
    }
    if (j == 0) {
        out[g * KK + 0] = sm0[0] + bc[0];
        out[g * KK + 1] = sm1[0] + bc[1];
    }
}

// ---------------- launch ----------------
extern "C" void kernel_launch(void* const* d_in, const int* in_sizes, int n_in,
                              void* d_out, int out_size) {
    const float* x        = (const float*)d_in[0];
    const void*  ei       = d_in[1];
    const void*  batch    = d_in[2];
    const float* clinical = (const float*)d_in[3];
    const float* W1 = (const float*)d_in[4];  const float* b1 = (const float*)d_in[5];
    const float* W2 = (const float*)d_in[6];  const float* b2 = (const float*)d_in[7];
    const float* W3 = (const float*)d_in[8];  const float* b3 = (const float*)d_in[9];
    const float* g1 = (const float*)d_in[10]; const float* be1 = (const float*)d_in[11];
    const float* g2 = (const float*)d_in[12]; const float* be2 = (const float*)d_in[13];
    const float* g3 = (const float*)d_in[14]; const float* be3 = (const float*)d_in[15];
    const float* Wc = (const float*)d_in[16]; const float* bc = (const float*)d_in[17];
    float* out = (float*)d_out;

    const int gemm_blocks = (NN + 127) / 128;   // 782
    const int e_blocks    = (EE + 255) / 256;   // 6250
    const int n_blocks    = (NN + 255) / 256;   // 391
    const size_t gemm_smem = SMEM_U32 * sizeof(uint32_t);   // 40 KB

    cudaFuncSetAttribute(k_gemm_tc<0>,
                         cudaFuncAttributeMaxDynamicSharedMemorySize, (int)gemm_smem);
    cudaFuncSetAttribute(k_gemm_tc<1>,
                         cudaFuncAttributeMaxDynamicSharedMemorySize, (int)gemm_smem);

    k_init<<<n_blocks, 256>>>((const int*)ei);
    k_hist<<<e_blocks, 256>>>(ei);
    k_scan1<<<SCAN_BLOCKS, 256>>>();
    k_scan3<<<SCAN_BLOCKS, 256>>>(batch);
    k_place<<<e_blocks, 256>>>(ei);

    // layer 1
    k_prepw1<<<64, 256>>>(W1);
    k_gemm_tc<0><<<gemm_blocks, 256, gemm_smem>>>(x);
    k_agg<false><<<AGG_BLOCKS, 256>>>(b1, batch, g1, be1);

    // layer 2
    k_prepw_aff_r<<<65, 256>>>(W2);
    k_gemm_tc<1><<<gemm_blocks, 256, gemm_smem>>>(nullptr);
    k_agg<false><<<AGG_BLOCKS, 256>>>(b2, batch, g2, be2);

    // layer 3
    k_prepw_aff_r<<<65, 256>>>(W3);
    k_gemm_tc<1><<<gemm_blocks, 256, gemm_smem>>>(nullptr);
    k_agg<true><<<AGG_BLOCKS, 256>>>(b3, batch, g3, be3);

    k_final<<<GG, 128>>>(clinical, Wc, bc, out);
}

// round 7
// speedup vs baseline: 1.0483x; 1.0483x over previous
#include <cuda_runtime.h>
#include <cuda_fp16.h>
#include <cstdint>

#define NN 100000
#define EE 1600000
#define HH 128
#define GG 256
#define CC 16
#define KK 2

#define SCAN_BLOCKS ((NN + 255) / 256)   // 391
#define AGG_BLOCKS 1024

// ---------------- device scratch (static, allowed) ----------------
__device__ __half g_xs16[(size_t)NN * HH]; // dis-scaled transformed features (fp16)
__device__ __half g_h16 [(size_t)NN * HH]; // layer activations (fp16)
__device__ float g_dis[NN];
__device__ int   g_deg[NN];
__device__ int   g_rowptr[NN + 1];
__device__ int   g_cursor[NN];
__device__ int   g_csrc[EE];
__device__ float g_stats[2 * HH];          // [0..127] sum, [128..255] sumsq
__device__ float g_bns[HH];                // BN affine scale
__device__ float g_bnt[HH];                // BN affine shift
__device__ float g_pool[GG * HH];
__device__ int   g_i64;                    // 1 if index tensors are int64
__device__ int   g_blk[SCAN_BLOCKS + 8];
__device__ int   g_blkoff[SCAN_BLOCKS + 8];
__device__ __half g_wh[HH * HH];           // W'^T hi fp16, layout [n][k]
__device__ __half g_wl[HH * HH];           // W'^T lo fp16 (residual)
__device__ float g_wr[HH];                 // r[n] = sum_k t[k] * W[k][n]
__device__ unsigned g_arr;                 // arrival counter

__device__ __forceinline__ long long idx_at(const void* p, long long i) {
    if (g_i64) return ((const long long*)p)[i];
    return (long long)((const int*)p)[i];
}

__device__ __forceinline__ void mma_f16(float* c, const uint32_t* a,
                                        uint32_t b0, uint32_t b1) {
    asm volatile(
        "mma.sync.aligned.m16n8k16.row.col.f32.f16.f16.f32 "
        "{%0,%1,%2,%3}, {%4,%5,%6,%7}, {%8,%9}, {%0,%1,%2,%3};\n"
        : "+f"(c[0]), "+f"(c[1]), "+f"(c[2]), "+f"(c[3])
        : "r"(a[0]), "r"(a[1]), "r"(a[2]), "r"(a[3]), "r"(b0), "r"(b1));
}

__device__ __forceinline__ uint32_t pack2(float a, float b) {
    __half2 h = __floats2half2_rn(a, b);
    return *(uint32_t*)&h;
}

// ---------------- init (+ index width detection in block 0) ----------------
__global__ void k_init(const int* ei) {
    int i = blockIdx.x * 256 + threadIdx.x;
    if (blockIdx.x == 0 && threadIdx.x < 32) {
        int lane = threadIdx.x;
        int v = ei[2 * lane + 1] | ei[2 * (lane + 32) + 1] |
                ei[2 * (lane + 64) + 1] | ei[2 * (lane + 96) + 1];
        unsigned m = __ballot_sync(0xffffffffu, v != 0);
        if (lane == 0) g_i64 = (m == 0) ? 1 : 0;
    }
    if (i < NN) g_deg[i] = 0;
    if (i < GG * HH) g_pool[i] = 0.f;
    if (i < 2 * HH) g_stats[i] = 0.f;
    if (i == 0) g_arr = 0u;
}

// ---------------- CSR build ----------------
__global__ void k_hist(const void* ei) {
    int e = blockIdx.x * 256 + threadIdx.x;
    if (e < EE) {
        int d = (int)idx_at(ei, (long long)EE + e);
        atomicAdd(&g_deg[d], 1);
    }
}

// pass 1 (+ merged pass 2 in last block): per-block sums, then scan of block sums
__global__ void k_scan1() {
    int tid = threadIdx.x;
    int i = blockIdx.x * 256 + tid;
    int v = (i < NN) ? g_deg[i] : 0;
#pragma unroll
    for (int o = 16; o; o >>= 1) v += __shfl_down_sync(0xffffffffu, v, o);
    __shared__ int ws[8];
    if ((tid & 31) == 0) ws[tid >> 5] = v;
    __syncthreads();
    if (tid < 8) {
        int s = ws[tid];
#pragma unroll
        for (int o = 4; o; o >>= 1) s += __shfl_down_sync(0xffu, s, o);
        if (tid == 0) g_blk[blockIdx.x] = s;
    }
    __threadfence();
    __syncthreads();
    __shared__ int isLast;
    if (tid == 0)
        isLast = (atomicAdd(&g_arr, 1u) == (unsigned)(gridDim.x - 1)) ? 1 : 0;
    __syncthreads();
    if (isLast) {
        __shared__ int s[256];
        int i0 = 2 * tid, i1 = 2 * tid + 1;
        int v0 = (i0 < SCAN_BLOCKS) ? g_blk[i0] : 0;
        int v1 = (i1 < SCAN_BLOCKS) ? g_blk[i1] : 0;
        int p = v0 + v1;
        s[tid] = p;
        __syncthreads();
        for (int d = 1; d < 256; d <<= 1) {
            int x = (tid >= d) ? s[tid - d] : 0;
            __syncthreads();
            s[tid] += x;
            __syncthreads();
        }
        int excl = s[tid] - p;
        if (i0 < SCAN_BLOCKS) g_blkoff[i0] = excl;
        if (i1 < SCAN_BLOCKS) g_blkoff[i1] = excl + v0;
        if (tid == 255) g_rowptr[NN] = s[255];
        if (tid == 0) g_arr = 0u;
    }
}

// pass 3: local scan + block offset -> rowptr/cursor; also dis
__global__ void k_scan3() {
    int tid = threadIdx.x;
    int i = blockIdx.x * 256 + tid;
    int v = (i < NN) ? g_deg[i] : 0;
    int x = v;
#pragma unroll
    for (int o = 1; o < 32; o <<= 1) {
        int y = __shfl_up_sync(0xffffffffu, x, o);
        if ((tid & 31) >= o) x += y;
    }
    __shared__ int ws[8];
    if ((tid & 31) == 31) ws[tid >> 5] = x;
    __syncthreads();
    if (tid < 8) {
        int s = ws[tid];
#pragma unroll
        for (int o = 1; o < 8; o <<= 1) {
            int y = __shfl_up_sync(0xffu, s, o);
            if (tid >= o) s += y;
        }
        ws[tid] = s;
    }
    __syncthreads();
    int warpoff = (tid >= 32) ? ws[(tid >> 5) - 1] : 0;
    int excl = x - v + warpoff + g_blkoff[blockIdx.x];
    if (i < NN) {
        g_rowptr[i] = excl;
        g_cursor[i] = excl;
        g_dis[i] = rsqrtf((float)v + 1.0f);
    }
}

__global__ void k_place(const void* ei) {
    int e = blockIdx.x * 256 + threadIdx.x;
    if (e < EE) {
        int d = (int)idx_at(ei, (long long)EE + e);
        int pos = atomicAdd(&g_cursor[d], 1);
        g_csrc[pos] = (int)idx_at(ei, (long long)e);
    }
}

// ---------------- W prep: double-fp16 split, transposed [n][k] ----------------
__global__ void k_prepw1(const float* __restrict__ W) {
    int idx = blockIdx.x * 256 + threadIdx.x;
    if (idx < HH * HH) {
        int k = idx >> 7, n = idx & 127;
        float v = W[idx];
        __half h = __float2half_rn(v);
        g_wh[n * HH + k] = h;
        g_wl[n * HH + k] = __float2half_rn(v - __half2float(h));
    }
    if (blockIdx.x == 0 && threadIdx.x < HH) g_wr[threadIdx.x] = 0.f;
}

// layers 2/3: fold BN scale into W rows + compute r; grid = 65 blocks
__global__ void k_prepw_aff_r(const float* __restrict__ W) {
    if (blockIdx.x < 64) {
        int idx = blockIdx.x * 256 + threadIdx.x;
        int k = idx >> 7, n = idx & 127;
        float v = W[idx] * g_bns[k];
        __half h = __float2half_rn(v);
        g_wh[n * HH + k] = h;
        g_wl[n * HH + k] = __float2half_rn(v - __half2float(h));
    } else if (threadIdx.x < HH) {
        int n = threadIdx.x;
        float r = 0.f;
#pragma unroll 4
        for (int k = 0; k < HH; k++) r = fmaf(g_bnt[k], W[k * HH + n], r);
        g_wr[n] = r;
    }
}

// ---------------- fp16 tensor-core GEMM: xs16 = dis * (A @ W' + r) ----------------
// MODE 0: A fp32 -> hi/lo fp16 split, 3 passes; MODE 1: A fp16 exact, 2 passes
#define ST 20
#define SA_H 0
#define SA_L (128 * ST)
#define SW_H (2 * 128 * ST)
#define SW_L (3 * 128 * ST)
#define SMEM_U32 (4 * 128 * ST)

template<int MODE>
__global__ void __launch_bounds__(256, 2) k_gemm_tc(const float* __restrict__ Ain) {
    extern __shared__ uint32_t sm[];
    int tid = threadIdx.x;
    int wid = tid >> 5, lane = tid & 31;
    int wm = wid >> 1, wn = wid & 1;        // 4 x 2 warp grid
    int ly = lane >> 2, lx = lane & 3;
    int rbase = blockIdx.x * 128;

    float acc[2][8][4];
#pragma unroll
    for (int mt = 0; mt < 2; mt++)
#pragma unroll
        for (int j = 0; j < 8; j++)
#pragma unroll
            for (int q = 0; q < 4; q++) acc[mt][j][q] = 0.f;

    for (int ch = 0; ch < 4; ch++) {
        int kbase = ch * 32;
#pragma unroll
        for (int i = 0; i < 2; i++) {
            int idx = i * 256 + tid;
            int m = idx >> 2, q = idx & 3;
            int gr = rbase + m;
            if (MODE == 0) {
                float4 v0 = make_float4(0.f, 0.f, 0.f, 0.f);
                float4 v1 = make_float4(0.f, 0.f, 0.f, 0.f);
                if (gr < NN) {
                    v0 = *(const float4*)&Ain[(size_t)gr * HH + kbase + 8 * q];
                    v1 = *(const float4*)&Ain[(size_t)gr * HH + kbase + 8 * q + 4];
                }
                __half h0 = __float2half_rn(v0.x), h1 = __float2half_rn(v0.y);
                __half h2 = __float2half_rn(v0.z), h3 = __float2half_rn(v0.w);
                __half h4 = __float2half_rn(v1.x), h5 = __float2half_rn(v1.y);
                __half h6 = __float2half_rn(v1.z), h7 = __float2half_rn(v1.w);
                uint4 hi = make_uint4(
                    pack2(__half2float(h0), __half2float(h1)),
                    pack2(__half2float(h2), __half2float(h3)),
                    pack2(__half2float(h4), __half2float(h5)),
                    pack2(__half2float(h6), __half2float(h7)));
                uint4 lo = make_uint4(
                    pack2(v0.x - __half2float(h0), v0.y - __half2float(h1)),
                    pack2(v0.z - __half2float(h2), v0.w - __half2float(h3)),
                    pack2(v1.x - __half2float(h4), v1.y - __half2float(h5)),
                    pack2(v1.z - __half2float(h6), v1.w - __half2float(h7)));
                *(uint4*)&sm[SA_H + m * ST + 4 * q] = hi;
                *(uint4*)&sm[SA_L + m * ST + 4 * q] = lo;
            } else {
                uint4 u = make_uint4(0u, 0u, 0u, 0u);
                if (gr < NN)
                    u = *(const uint4*)&g_h16[(size_t)gr * HH + kbase + 8 * q];
                *(uint4*)&sm[SA_H + m * ST + 4 * q] = u;
            }
        }
#pragma unroll
        for (int i = 0; i < 2; i++) {
            int idx = i * 256 + tid;
            int n = idx >> 2, q = idx & 3;
            *(uint4*)&sm[SW_H + n * ST + 4 * q] =
                *(const uint4*)&g_wh[n * HH + kbase + 8 * q];
            *(uint4*)&sm[SW_L + n * ST + 4 * q] =
                *(const uint4*)&g_wl[n * HH + kbase + 8 * q];
        }
        __syncthreads();

#pragma unroll
        for (int ks = 0; ks < 2; ks++) {
            int koff = ks * 8;
            uint32_t ah[2][4], al[2][4];
#pragma unroll
            for (int mt = 0; mt < 2; mt++) {
                int base = (wm * 32 + mt * 16 + ly) * ST + koff + lx;
                ah[mt][0] = sm[SA_H + base];
                ah[mt][1] = sm[SA_H + base + 8 * ST];
                ah[mt][2] = sm[SA_H + base + 4];
                ah[mt][3] = sm[SA_H + base + 8 * ST + 4];
                if (MODE == 0) {
                    al[mt][0] = sm[SA_L + base];
                    al[mt][1] = sm[SA_L + base + 8 * ST];
                    al[mt][2] = sm[SA_L + base + 4];
                    al[mt][3] = sm[SA_L + base + 8 * ST + 4];
                }
            }
#pragma unroll
            for (int j = 0; j < 8; j++) {
                int bbase = (wn * 64 + 8 * j + ly) * ST + koff + lx;
                uint32_t bh0 = sm[SW_H + bbase];
                uint32_t bh1 = sm[SW_H + bbase + 4];
                uint32_t bl0 = sm[SW_L + bbase];
                uint32_t bl1 = sm[SW_L + bbase + 4];
#pragma unroll
                for (int mt = 0; mt < 2; mt++) {
                    mma_f16(acc[mt][j], ah[mt], bh0, bh1);
                    mma_f16(acc[mt][j], ah[mt], bl0, bl1);
                    if (MODE == 0) mma_f16(acc[mt][j], al[mt], bh0, bh1);
                }
            }
        }
        __syncthreads();
    }

#pragma unroll
    for (int mt = 0; mt < 2; mt++) {
        int r0 = rbase + wm * 32 + mt * 16 + ly;
        int r1 = r0 + 8;
        float d0 = (r0 < NN) ? g_dis[r0] : 0.f;
        float d1 = (r1 < NN) ? g_dis[r1] : 0.f;
#pragma unroll
        for (int j = 0; j < 8; j++) {
            int cb = wn * 64 + 8 * j + 2 * lx;
            float ra = g_wr[cb], rb = g_wr[cb + 1];
            if (r0 < NN) {
                __half2 o = __floats2half2_rn(d0 * (acc[mt][j][0] + ra),
                                              d0 * (acc[mt][j][1] + rb));
                *(__half2*)&g_xs16[(size_t)r0 * HH + cb] = o;
            }
            if (r1 < NN) {
                __half2 o = __floats2half2_rn(d1 * (acc[mt][j][2] + ra),
                                              d1 * (acc[mt][j][3] + rb));
                *(__half2*)&g_xs16[(size_t)r1 * HH + cb] = o;
            }
        }
    }
}

// ------- aggregation + relu + BN stats (+ pooling on last layer) + BN solve -------
#define ACCS(u0, u1, X, Y, Z, W) { \
    float2 t0 = __half22float2(*(__half2*)&(u0)); \
    float2 t1 = __half22float2(*(__half2*)&(u1)); \
    X += t0.x; Y += t0.y; Z += t1.x; W += t1.y; }

template<bool LAST>
__global__ void __launch_bounds__(256) k_agg(const float* __restrict__ bias,
                                             const void* __restrict__ batch,
                                             const float* __restrict__ gamma,
                                             const float* __restrict__ beta) {
    int tid = threadIdx.x;
    int wid = tid >> 5, lane = tid & 31;
    float4 b4 = ((const float4*)bias)[lane];
    float s0 = 0.f, s1 = 0.f, s2 = 0.f, s3 = 0.f;
    float q0 = 0.f, q1 = 0.f, q2 = 0.f, q3 = 0.f;
    const uint2* xsv = (const uint2*)g_xs16;

    for (long long i = (long long)blockIdx.x * 8 + wid; i < NN;
         i += (long long)AGG_BLOCKS * 8) {
        uint2 u = xsv[i * 32 + lane];                 // self term
        float ax0, ay0, az0, aw0;
        float ax1 = 0.f, ay1 = 0.f, az1 = 0.f, aw1 = 0.f;
        {
            float2 a0 = __half22float2(*(__half2*)&u.x);
            float2 a1 = __half22float2(*(__half2*)&u.y);
            ax0 = a0.x; ay0 = a0.y; az0 = a1.x; aw0 = a1.y;
        }
        int e0 = g_rowptr[i], e1 = g_rowptr[i + 1];
        int e = e0;
        for (; e + 4 <= e1; e += 4) {
            int sA = g_csrc[e], sB = g_csrc[e + 1];
            int sC = g_csrc[e + 2], sD = g_csrc[e + 3];
            uint2 vA = xsv[(long long)sA * 32 + lane];
            uint2 vB = xsv[(long long)sB * 32 + lane];
            uint2 vC = xsv[(long long)sC * 32 + lane];
            uint2 vD = xsv[(long long)sD * 32 + lane];
            ACCS(vA.x, vA.y, ax0, ay0, az0, aw0);
            ACCS(vB.x, vB.y, ax1, ay1, az1, aw1);
            ACCS(vC.x, vC.y, ax0, ay0, az0, aw0);
            ACCS(vD.x, vD.y, ax1, ay1, az1, aw1);
        }
        for (; e < e1; e++) {
            int s = g_csrc[e];
            uint2 v = xsv[(long long)s * 32 + lane];
            ACCS(v.x, v.y, ax0, ay0, az0, aw0);
        }
        float acx = ax0 + ax1, acy = ay0 + ay1;
        float acz = az0 + az1, acw = aw0 + aw1;
        float d = g_dis[i];
        float yx = fmaxf(fmaf(d, acx, b4.x), 0.f);
        float yy = fmaxf(fmaf(d, acy, b4.y), 0.f);
        float yz = fmaxf(fmaf(d, acz, b4.z), 0.f);
        float yw = fmaxf(fmaf(d, acw, b4.w), 0.f);
        if (!LAST) {
            uint2 o;
            *(__half2*)&o.x = __floats2half2_rn(yx, yy);
            *(__half2*)&o.y = __floats2half2_rn(yz, yw);
            ((uint2*)g_h16)[i * 32 + lane] = o;
        } else {
            int g = (int)idx_at(batch, i);
            float* p = &g_pool[g * HH + lane * 4];
            atomicAdd(p + 0, yx);
            atomicAdd(p + 1, yy);
            atomicAdd(p + 2, yz);
            atomicAdd(p + 3, yw);
        }
        s0 += yx; s1 += yy; s2 += yz; s3 += yw;
        q0 += yx * yx; q1 += yy * yy; q2 += yz * yz; q3 += yw * yw;
    }
    __shared__ float red[2 * HH];
    red[tid] = 0.f;
    __syncthreads();
    atomicAdd(&red[lane * 4 + 0], s0);
    atomicAdd(&red[lane * 4 + 1], s1);
    atomicAdd(&red[lane * 4 + 2], s2);
    atomicAdd(&red[lane * 4 + 3], s3);
    atomicAdd(&red[HH + lane * 4 + 0], q0);
    atomicAdd(&red[HH + lane * 4 + 1], q1);
    atomicAdd(&red[HH + lane * 4 + 2], q2);
    atomicAdd(&red[HH + lane * 4 + 3], q3);
    __syncthreads();
    atomicAdd(&g_stats[tid], red[tid]);
    __threadfence();
    __syncthreads();
    __shared__ int isLast;
    if (tid == 0)
        isLast = (atomicAdd(&g_arr, 1u) == (unsigned)(AGG_BLOCKS - 1)) ? 1 : 0;
    __syncthreads();
    if (isLast) {
        if (tid < HH) {
            float m = g_stats[tid] * (1.0f / NN);
            float v = g_stats[HH + tid] * (1.0f / NN) - m * m;
            v = fmaxf(v, 0.f);
            float s = gamma[tid] * rsqrtf(v + 1e-5f);
            g_bns[tid] = s;
            g_bnt[tid] = beta[tid] - m * s;
            g_stats[tid] = 0.f;
            g_stats[HH + tid] = 0.f;
        }
        if (tid == 0) g_arr = 0u;
    }
}

// ---------------- final head: pooled(BN3) ++ clinical -> linear ----------------
// per-graph node count computed from sorted batch via binary search (no atomics)
__device__ __forceinline__ int lb_batch(const void* batch, int val) {
    int lo = 0, hi = NN;
    while (lo < hi) {
        int mid = (lo + hi) >> 1;
        if ((int)idx_at(batch, mid) < val) lo = mid + 1;
        else hi = mid;
    }
    return lo;
}

__global__ void k_final(const void* __restrict__ batch,
                        const float* __restrict__ clinical,
                        const float* __restrict__ Wc,
                        const float* __restrict__ bc,
                        float* __restrict__ out) {
    int g = blockIdx.x, j = threadIdx.x;   // 128 threads
    __shared__ float cnt_s;
    if (j == 0) {
        int c = lb_batch(batch, g + 1) - lb_batch(batch, g);
        cnt_s = fmaxf((float)c, 1.0f);
    }
    __syncthreads();
    float p = g_pool[g * HH + j] / cnt_s;
    p = fmaf(p, g_bns[j], g_bnt[j]);
    float r0 = p * Wc[j * KK + 0];
    float r1 = p * Wc[j * KK + 1];
    if (j < CC) {
        float cl = clinical[g * CC + j];
        r0 = fmaf(cl, Wc[(HH + j) * KK + 0], r0);
        r1 = fmaf(cl, Wc[(HH + j) * KK + 1], r1);
    }
    __shared__ float sm0[128], sm1[128];
    sm0[j] = r0; sm1[j] = r1;
    __syncthreads();
    for (int d = 64; d > 0; d >>= 1) {
        if (j < d) { sm0[j] += sm0[j + d]; sm1[j] += sm1[j + d]; }
        __syncthreads();
    }
    if (j == 0) {
        out[g * KK + 0] = sm0[0] + bc[0];
        out[g * KK + 1] = sm1[0] + bc[1];
    }
}

// ---------------- launch ----------------
extern "C" void kernel_launch(void* const* d_in, const int* in_sizes, int n_in,
                              void* d_out, int out_size) {
    const float* x        = (const float*)d_in[0];
    const void*  ei       = d_in[1];
    const void*  batch    = d_in[2];
    const float* clinical = (const float*)d_in[3];
    const float* W1 = (const float*)d_in[4];  const float* b1 = (const float*)d_in[5];
    const float* W2 = (const float*)d_in[6];  const float* b2 = (const float*)d_in[7];
    const float* W3 = (const float*)d_in[8];  const float* b3 = (const float*)d_in[9];
    const float* g1 = (const float*)d_in[10]; const float* be1 = (const float*)d_in[11];
    const float* g2 = (const float*)d_in[12]; const float* be2 = (const float*)d_in[13];
    const float* g3 = (const float*)d_in[14]; const float* be3 = (const float*)d_in[15];
    const float* Wc = (const float*)d_in[16]; const float* bc = (const float*)d_in[17];
    float* out = (float*)d_out;

    const int gemm_blocks = (NN + 127) / 128;   // 782
    const int e_blocks    = (EE + 255) / 256;   // 6250
    const int n_blocks    = (NN + 255) / 256;   // 391
    const size_t gemm_smem = SMEM_U32 * sizeof(uint32_t);   // 40 KB

    cudaFuncSetAttribute(k_gemm_tc<0>,
                         cudaFuncAttributeMaxDynamicSharedMemorySize, (int)gemm_smem);
    cudaFuncSetAttribute(k_gemm_tc<1>,
                         cudaFuncAttributeMaxDynamicSharedMemorySize, (int)gemm_smem);

    k_init<<<n_blocks, 256>>>((const int*)ei);
    k_hist<<<e_blocks, 256>>>(ei);
    k_scan1<<<SCAN_BLOCKS, 256>>>();
    k_scan3<<<SCAN_BLOCKS, 256>>>();
    k_place<<<e_blocks, 256>>>(ei);

    // layer 1
    k_prepw1<<<64, 256>>>(W1);
    k_gemm_tc<0><<<gemm_blocks, 256, gemm_smem>>>(x);
    k_agg<false><<<AGG_BLOCKS, 256>>>(b1, batch, g1, be1);

    // layer 2
    k_prepw_aff_r<<<65, 256>>>(W2);
    k_gemm_tc<1><<<gemm_blocks, 256, gemm_smem>>>(nullptr);
    k_agg<false><<<AGG_BLOCKS, 256>>>(b2, batch, g2, be2);

    // layer 3
    k_prepw_aff_r<<<65, 256>>>(W3);
    k_gemm_tc<1><<<gemm_blocks, 256, gemm_smem>>>(nullptr);
    k_agg<true><<<AGG_BLOCKS, 256>>>(b3, batch, g3, be3);

    k_final<<<GG, 128>>>(batch, clinical, Wc, bc, out);
}

// round 8
// speedup vs baseline: 1.4119x; 1.3468x over previous
#include <cuda_runtime.h>
#include <cuda_fp16.h>
#include <cstdint>

#define NN 100000
#define EE 1600000
#define HH 128
#define GG 256
#define CC 16
#define KK 2

#define SCAN_BLOCKS ((NN + 255) / 256)   // 391
#define AGG_BLOCKS 1024
#define AGG_WARPS (AGG_BLOCKS * 8)
#define AGG_CHUNK ((NN + AGG_WARPS - 1) / AGG_WARPS)   // 13

// ---------------- device scratch (static, allowed) ----------------
__device__ __half g_xs16[(size_t)NN * HH]; // dis-scaled transformed features (fp16)
__device__ __half g_h16 [(size_t)NN * HH]; // layer activations (fp16)
__device__ float g_dis[NN];
__device__ int   g_deg[NN];
__device__ int   g_rowptr[NN + 1];
__device__ int   g_cursor[NN];
__device__ int   g_csrc[EE];
__device__ float g_stats[2 * HH];          // [0..127] sum, [128..255] sumsq
__device__ float g_bns[HH];                // BN affine scale
__device__ float g_bnt[HH];                // BN affine shift
__device__ float g_pool[GG * HH];
__device__ int   g_i64;                    // 1 if index tensors are int64
__device__ int   g_blk[SCAN_BLOCKS + 8];
__device__ int   g_blkoff[SCAN_BLOCKS + 8];
__device__ __half g_wh[HH * HH];           // W'^T hi fp16, layout [n][k]
__device__ __half g_wl[HH * HH];           // W'^T lo fp16 (residual)
__device__ float g_wr[HH];                 // r[n] = sum_k t[k] * W[k][n]
__device__ unsigned g_arr;                 // arrival counter

__device__ __forceinline__ long long idx_at(const void* p, long long i) {
    if (g_i64) return ((const long long*)p)[i];
    return (long long)((const int*)p)[i];
}

__device__ __forceinline__ void mma_f16(float* c, const uint32_t* a,
                                        uint32_t b0, uint32_t b1) {
    asm volatile(
        "mma.sync.aligned.m16n8k16.row.col.f32.f16.f16.f32 "
        "{%0,%1,%2,%3}, {%4,%5,%6,%7}, {%8,%9}, {%0,%1,%2,%3};\n"
        : "+f"(c[0]), "+f"(c[1]), "+f"(c[2]), "+f"(c[3])
        : "r"(a[0]), "r"(a[1]), "r"(a[2]), "r"(a[3]), "r"(b0), "r"(b1));
}

__device__ __forceinline__ uint32_t pack2(float a, float b) {
    __half2 h = __floats2half2_rn(a, b);
    return *(uint32_t*)&h;
}

__device__ __forceinline__ void cpa16(uint32_t dst, const void* src, bool pred) {
    asm volatile("cp.async.cg.shared.global [%0], [%1], 16, %2;\n"
                 :: "r"(dst), "l"(src), "r"(pred ? 16 : 0));
}
__device__ __forceinline__ void cpa_commit() {
    asm volatile("cp.async.commit_group;\n");
}
template<int N>
__device__ __forceinline__ void cpa_wait() {
    asm volatile("cp.async.wait_group %0;\n" :: "n"(N));
}

// ---------------- init (+ index width detection in block 0) ----------------
__global__ void k_init(const int* ei) {
    int i = blockIdx.x * 256 + threadIdx.x;
    if (blockIdx.x == 0 && threadIdx.x < 32) {
        int lane = threadIdx.x;
        int v = ei[2 * lane + 1] | ei[2 * (lane + 32) + 1] |
                ei[2 * (lane + 64) + 1] | ei[2 * (lane + 96) + 1];
        unsigned m = __ballot_sync(0xffffffffu, v != 0);
        if (lane == 0) g_i64 = (m == 0) ? 1 : 0;
    }
    if (i < NN) g_deg[i] = 0;
    if (i < GG * HH) g_pool[i] = 0.f;
    if (i < 2 * HH) g_stats[i] = 0.f;
    if (i == 0) g_arr = 0u;
}

// ---------------- CSR build ----------------
__global__ void k_hist(const void* ei) {
    int e = blockIdx.x * 256 + threadIdx.x;
    if (e < EE) {
        int d = (int)idx_at(ei, (long long)EE + e);
        atomicAdd(&g_deg[d], 1);
    }
}

// pass 1 (+ merged pass 2 in last block)
__global__ void k_scan1() {
    int tid = threadIdx.x;
    int i = blockIdx.x * 256 + tid;
    int v = (i < NN) ? g_deg[i] : 0;
#pragma unroll
    for (int o = 16; o; o >>= 1) v += __shfl_down_sync(0xffffffffu, v, o);
    __shared__ int ws[8];
    if ((tid & 31) == 0) ws[tid >> 5] = v;
    __syncthreads();
    if (tid < 8) {
        int s = ws[tid];
#pragma unroll
        for (int o = 4; o; o >>= 1) s += __shfl_down_sync(0xffu, s, o);
        if (tid == 0) g_blk[blockIdx.x] = s;
    }
    __threadfence();
    __syncthreads();
    __shared__ int isLast;
    if (tid == 0)
        isLast = (atomicAdd(&g_arr, 1u) == (unsigned)(gridDim.x - 1)) ? 1 : 0;
    __syncthreads();
    if (isLast) {
        __shared__ int s[256];
        int i0 = 2 * tid, i1 = 2 * tid + 1;
        int v0 = (i0 < SCAN_BLOCKS) ? g_blk[i0] : 0;
        int v1 = (i1 < SCAN_BLOCKS) ? g_blk[i1] : 0;
        int p = v0 + v1;
        s[tid] = p;
        __syncthreads();
        for (int d = 1; d < 256; d <<= 1) {
            int x = (tid >= d) ? s[tid - d] : 0;
            __syncthreads();
            s[tid] += x;
            __syncthreads();
        }
        int excl = s[tid] - p;
        if (i0 < SCAN_BLOCKS) g_blkoff[i0] = excl;
        if (i1 < SCAN_BLOCKS) g_blkoff[i1] = excl + v0;
        if (tid == 255) g_rowptr[NN] = s[255];
        if (tid == 0) g_arr = 0u;
    }
}

// pass 3: local scan + block offset -> rowptr/cursor; also dis
__global__ void k_scan3() {
    int tid = threadIdx.x;
    int i = blockIdx.x * 256 + tid;
    int v = (i < NN) ? g_deg[i] : 0;
    int x = v;
#pragma unroll
    for (int o = 1; o < 32; o <<= 1) {
        int y = __shfl_up_sync(0xffffffffu, x, o);
        if ((tid & 31) >= o) x += y;
    }
    __shared__ int ws[8];
    if ((tid & 31) == 31) ws[tid >> 5] = x;
    __syncthreads();
    if (tid < 8) {
        int s = ws[tid];
#pragma unroll
        for (int o = 1; o < 8; o <<= 1) {
            int y = __shfl_up_sync(0xffu, s, o);
            if (tid >= o) s += y;
        }
        ws[tid] = s;
    }
    __syncthreads();
    int warpoff = (tid >= 32) ? ws[(tid >> 5) - 1] : 0;
    int excl = x - v + warpoff + g_blkoff[blockIdx.x];
    if (i < NN) {
        g_rowptr[i] = excl;
        g_cursor[i] = excl;
        g_dis[i] = rsqrtf((float)v + 1.0f);
    }
}

__global__ void k_place(const void* ei) {
    int e = blockIdx.x * 256 + threadIdx.x;
    if (e < EE) {
        int d = (int)idx_at(ei, (long long)EE + e);
        int pos = atomicAdd(&g_cursor[d], 1);
        g_csrc[pos] = (int)idx_at(ei, (long long)e);
    }
}

// ---------------- W prep: double-fp16 split, transposed [n][k] ----------------
__global__ void k_prepw1(const float* __restrict__ W) {
    int idx = blockIdx.x * 256 + threadIdx.x;
    if (idx < HH * HH) {
        int k = idx >> 7, n = idx & 127;
        float v = W[idx];
        __half h = __float2half_rn(v);
        g_wh[n * HH + k] = h;
        g_wl[n * HH + k] = __float2half_rn(v - __half2float(h));
    }
    if (blockIdx.x == 0 && threadIdx.x < HH) g_wr[threadIdx.x] = 0.f;
}

__global__ void k_prepw_aff_r(const float* __restrict__ W) {
    if (blockIdx.x < 64) {
        int idx = blockIdx.x * 256 + threadIdx.x;
        int k = idx >> 7, n = idx & 127;
        float v = W[idx] * g_bns[k];
        __half h = __float2half_rn(v);
        g_wh[n * HH + k] = h;
        g_wl[n * HH + k] = __float2half_rn(v - __half2float(h));
    } else if (threadIdx.x < HH) {
        int n = threadIdx.x;
        float r = 0.f;
#pragma unroll 4
        for (int k = 0; k < HH; k++) r = fmaf(g_bnt[k], W[k * HH + n], r);
        g_wr[n] = r;
    }
}

// ---------------- fp16 tensor-core GEMM: xs16 = dis * (A @ W' + r) ----------------
// MODE 0: A fp32 -> hi/lo fp16 split, 3 passes, synchronous smem fill.
// MODE 1: A fp16 exact, 2 passes, cp.async 2-stage double buffer.
#define ST 20
#define TS (128 * ST)
// MODE0 layout (single buffer): SA_H, SA_L, SW_H, SW_L
#define SA_H 0
#define SA_L TS
#define SW_H (2 * TS)
#define SW_L (3 * TS)
#define SMEM0_U32 (4 * TS)          // 40 KB
// MODE1 layout (double buffer): per buf {A, WH, WL}, stride 3*TS
#define BUFS (3 * TS)
#define SMEM1_U32 (2 * BUFS)        // 60 KB

template<int MODE>
__global__ void __launch_bounds__(256, 2) k_gemm_tc(const float* __restrict__ Ain) {
    extern __shared__ uint32_t sm[];
    int tid = threadIdx.x;
    int wid = tid >> 5, lane = tid & 31;
    int wm = wid >> 1, wn = wid & 1;        // 4 x 2 warp grid
    int ly = lane >> 2, lx = lane & 3;
    int rbase = blockIdx.x * 128;

    float acc[2][8][4];
#pragma unroll
    for (int mt = 0; mt < 2; mt++)
#pragma unroll
        for (int j = 0; j < 8; j++)
#pragma unroll
            for (int q = 0; q < 4; q++) acc[mt][j][q] = 0.f;

    if (MODE == 0) {
        for (int ch = 0; ch < 4; ch++) {
            int kbase = ch * 32;
#pragma unroll
            for (int i = 0; i < 2; i++) {
                int idx = i * 256 + tid;
                int m = idx >> 2, q = idx & 3;
                int gr = rbase + m;
                float4 v0 = make_float4(0.f, 0.f, 0.f, 0.f);
                float4 v1 = make_float4(0.f, 0.f, 0.f, 0.f);
                if (gr < NN) {
                    v0 = *(const float4*)&Ain[(size_t)gr * HH + kbase + 8 * q];
                    v1 = *(const float4*)&Ain[(size_t)gr * HH + kbase + 8 * q + 4];
                }
                __half h0 = __float2half_rn(v0.x), h1 = __float2half_rn(v0.y);
                __half h2 = __float2half_rn(v0.z), h3 = __float2half_rn(v0.w);
                __half h4 = __float2half_rn(v1.x), h5 = __float2half_rn(v1.y);
                __half h6 = __float2half_rn(v1.z), h7 = __float2half_rn(v1.w);
                uint4 hi = make_uint4(
                    pack2(__half2float(h0), __half2float(h1)),
                    pack2(__half2float(h2), __half2float(h3)),
                    pack2(__half2float(h4), __half2float(h5)),
                    pack2(__half2float(h6), __half2float(h7)));
                uint4 lo = make_uint4(
                    pack2(v0.x - __half2float(h0), v0.y - __half2float(h1)),
                    pack2(v0.z - __half2float(h2), v0.w - __half2float(h3)),
                    pack2(v1.x - __half2float(h4), v1.y - __half2float(h5)),
                    pack2(v1.z - __half2float(h6), v1.w - __half2float(h7)));
                *(uint4*)&sm[SA_H + m * ST + 4 * q] = hi;
                *(uint4*)&sm[SA_L + m * ST + 4 * q] = lo;
            }
#pragma unroll
            for (int i = 0; i < 2; i++) {
                int idx = i * 256 + tid;
                int n = idx >> 2, q = idx & 3;
                *(uint4*)&sm[SW_H + n * ST + 4 * q] =
                    *(const uint4*)&g_wh[n * HH + kbase + 8 * q];
                *(uint4*)&sm[SW_L + n * ST + 4 * q] =
                    *(const uint4*)&g_wl[n * HH + kbase + 8 * q];
            }
            __syncthreads();
#pragma unroll
            for (int ks = 0; ks < 2; ks++) {
                int koff = ks * 8;
                uint32_t ah[2][4], al[2][4];
#pragma unroll
                for (int mt = 0; mt < 2; mt++) {
                    int base = (wm * 32 + mt * 16 + ly) * ST + koff + lx;
                    ah[mt][0] = sm[SA_H + base];
                    ah[mt][1] = sm[SA_H + base + 8 * ST];
                    ah[mt][2] = sm[SA_H + base + 4];
                    ah[mt][3] = sm[SA_H + base + 8 * ST + 4];
                    al[mt][0] = sm[SA_L + base];
                    al[mt][1] = sm[SA_L + base + 8 * ST];
                    al[mt][2] = sm[SA_L + base + 4];
                    al[mt][3] = sm[SA_L + base + 8 * ST + 4];
                }
#pragma unroll
                for (int j = 0; j < 8; j++) {
                    int bbase = (wn * 64 + 8 * j + ly) * ST + koff + lx;
                    uint32_t bh0 = sm[SW_H + bbase];
                    uint32_t bh1 = sm[SW_H + bbase + 4];
                    uint32_t bl0 = sm[SW_L + bbase];
                    uint32_t bl1 = sm[SW_L + bbase + 4];
#pragma unroll
                    for (int mt = 0; mt < 2; mt++) {
                        mma_f16(acc[mt][j], ah[mt], bh0, bh1);
                        mma_f16(acc[mt][j], ah[mt], bl0, bl1);
                        mma_f16(acc[mt][j], al[mt], bh0, bh1);
                    }
                }
            }
            __syncthreads();
        }
    } else {
        // cp.async 2-stage pipeline
        uint32_t sbase = (uint32_t)__cvta_generic_to_shared((void*)sm);
        int m_ = tid >> 2, q_ = tid & 3;           // reused thread mapping
        int m2 = (256 + tid) >> 2, q2 = (256 + tid) & 3;
#define ISSUE_CHUNK(CH, BUF) { \
        int kb = (CH) * 32; int bo = (BUF) * BUFS; \
        { int gr = rbase + m_; bool p = gr < NN; \
          const __half* s = p ? &g_h16[(size_t)gr * HH + kb + 8 * q_] : &g_h16[0]; \
          cpa16(sbase + 4 * (bo + m_ * ST + 4 * q_), s, p); } \
        { int gr = rbase + m2; bool p = gr < NN; \
          const __half* s = p ? &g_h16[(size_t)gr * HH + kb + 8 * q2] : &g_h16[0]; \
          cpa16(sbase + 4 * (bo + m2 * ST + 4 * q2), s, p); } \
        cpa16(sbase + 4 * (bo + TS + m_ * ST + 4 * q_),      &g_wh[m_ * HH + kb + 8 * q_], true); \
        cpa16(sbase + 4 * (bo + TS + m2 * ST + 4 * q2),      &g_wh[m2 * HH + kb + 8 * q2], true); \
        cpa16(sbase + 4 * (bo + 2 * TS + m_ * ST + 4 * q_),  &g_wl[m_ * HH + kb + 8 * q_], true); \
        cpa16(sbase + 4 * (bo + 2 * TS + m2 * ST + 4 * q2),  &g_wl[m2 * HH + kb + 8 * q2], true); \
        cpa_commit(); }

        ISSUE_CHUNK(0, 0);
#pragma unroll
        for (int ch = 0; ch < 4; ch++) {
            int buf = ch & 1;
            if (ch < 3) { ISSUE_CHUNK(ch + 1, buf ^ 1); cpa_wait<1>(); }
            else cpa_wait<0>();
            __syncthreads();
            int bo = buf * BUFS;
#pragma unroll
            for (int ks = 0; ks < 2; ks++) {
                int koff = ks * 8;
                uint32_t ah[2][4];
#pragma unroll
                for (int mt = 0; mt < 2; mt++) {
                    int base = bo + (wm * 32 + mt * 16 + ly) * ST + koff + lx;
                    ah[mt][0] = sm[base];
                    ah[mt][1] = sm[base + 8 * ST];
                    ah[mt][2] = sm[base + 4];
                    ah[mt][3] = sm[base + 8 * ST + 4];
                }
#pragma unroll
                for (int j = 0; j < 8; j++) {
                    int bbase = bo + TS + (wn * 64 + 8 * j + ly) * ST + koff + lx;
                    uint32_t bh0 = sm[bbase];
                    uint32_t bh1 = sm[bbase + 4];
                    uint32_t bl0 = sm[bbase + TS];
                    uint32_t bl1 = sm[bbase + TS + 4];
#pragma unroll
                    for (int mt = 0; mt < 2; mt++) {
                        mma_f16(acc[mt][j], ah[mt], bh0, bh1);
                        mma_f16(acc[mt][j], ah[mt], bl0, bl1);
                    }
                }
            }
            __syncthreads();
        }
#undef ISSUE_CHUNK
    }

    // epilogue: xs16 = dis[r] * (acc + wr)
#pragma unroll
    for (int mt = 0; mt < 2; mt++) {
        int r0 = rbase + wm * 32 + mt * 16 + ly;
        int r1 = r0 + 8;
        float d0 = (r0 < NN) ? g_dis[r0] : 0.f;
        float d1 = (r1 < NN) ? g_dis[r1] : 0.f;
#pragma unroll
        for (int j = 0; j < 8; j++) {
            int cb = wn * 64 + 8 * j + 2 * lx;
            float ra = g_wr[cb], rb = g_wr[cb + 1];
            if (r0 < NN) {
                __half2 o = __floats2half2_rn(d0 * (acc[mt][j][0] + ra),
                                              d0 * (acc[mt][j][1] + rb));
                *(__half2*)&g_xs16[(size_t)r0 * HH + cb] = o;
            }
            if (r1 < NN) {
                __half2 o = __floats2half2_rn(d1 * (acc[mt][j][2] + ra),
                                              d1 * (acc[mt][j][3] + rb));
                *(__half2*)&g_xs16[(size_t)r1 * HH + cb] = o;
            }
        }
    }
}

// ------- aggregation + relu + BN stats (+ pooling on last layer) + BN solve -------
// Contiguous chunk per warp: node range [wgl*CH, min(+CH, NN)).
#define ACCS(u0, u1, X, Y, Z, W) { \
    float2 t0 = __half22float2(*(__half2*)&(u0)); \
    float2 t1 = __half22float2(*(__half2*)&(u1)); \
    X += t0.x; Y += t0.y; Z += t1.x; W += t1.y; }

template<bool LAST>
__global__ void __launch_bounds__(256) k_agg(const float* __restrict__ bias,
                                             const void* __restrict__ batch,
                                             const float* __restrict__ gamma,
                                             const float* __restrict__ beta) {
    int tid = threadIdx.x;
    int wid = tid >> 5, lane = tid & 31;
    float4 b4 = ((const float4*)bias)[lane];
    float s0 = 0.f, s1 = 0.f, s2 = 0.f, s3 = 0.f;
    float q0 = 0.f, q1 = 0.f, q2 = 0.f, q3 = 0.f;
    const uint2* xsv = (const uint2*)g_xs16;

    int wgl = blockIdx.x * 8 + wid;
    int istart = wgl * AGG_CHUNK;
    int iend = istart + AGG_CHUNK;
    if (iend > NN) iend = NN;

    // pool run-accumulation state (LAST only)
    int curg = -1;
    float px = 0.f, py = 0.f, pz = 0.f, pw = 0.f;

    for (int i = istart; i < iend; i++) {
        uint2 u = xsv[(long long)i * 32 + lane];      // self term
        float ax0, ay0, az0, aw0;
        float ax1 = 0.f, ay1 = 0.f, az1 = 0.f, aw1 = 0.f;
        {
            float2 a0 = __half22float2(*(__half2*)&u.x);
            float2 a1 = __half22float2(*(__half2*)&u.y);
            ax0 = a0.x; ay0 = a0.y; az0 = a1.x; aw0 = a1.y;
        }
        int e0 = g_rowptr[i], e1 = g_rowptr[i + 1];
        int e = e0;
        for (; e + 4 <= e1; e += 4) {
            int sA = g_csrc[e], sB = g_csrc[e + 1];
            int sC = g_csrc[e + 2], sD = g_csrc[e + 3];
            uint2 vA = xsv[(long long)sA * 32 + lane];
            uint2 vB = xsv[(long long)sB * 32 + lane];
            uint2 vC = xsv[(long long)sC * 32 + lane];
            uint2 vD = xsv[(long long)sD * 32 + lane];
            ACCS(vA.x, vA.y, ax0, ay0, az0, aw0);
            ACCS(vB.x, vB.y, ax1, ay1, az1, aw1);
            ACCS(vC.x, vC.y, ax0, ay0, az0, aw0);
            ACCS(vD.x, vD.y, ax1, ay1, az1, aw1);
        }
        for (; e < e1; e++) {
            int s = g_csrc[e];
            uint2 v = xsv[(long long)s * 32 + lane];
            ACCS(v.x, v.y, ax0, ay0, az0, aw0);
        }
        float acx = ax0 + ax1, acy = ay0 + ay1;
        float acz = az0 + az1, acw = aw0 + aw1;
        float d = g_dis[i];
        float yx = fmaxf(fmaf(d, acx, b4.x), 0.f);
        float yy = fmaxf(fmaf(d, acy, b4.y), 0.f);
        float yz = fmaxf(fmaf(d, acz, b4.z), 0.f);
        float yw = fmaxf(fmaf(d, acw, b4.w), 0.f);
        if (!LAST) {
            uint2 o;
            *(__half2*)&o.x = __floats2half2_rn(yx, yy);
            *(__half2*)&o.y = __floats2half2_rn(yz, yw);
            ((uint2*)g_h16)[(long long)i * 32 + lane] = o;
        } else {
            int g = (int)idx_at(batch, i);
            if (g != curg) {
                if (curg >= 0) {
                    float* p = &g_pool[curg * HH + lane * 4];
                    atomicAdd(p + 0, px); atomicAdd(p + 1, py);
                    atomicAdd(p + 2, pz); atomicAdd(p + 3, pw);
                }
                curg = g; px = py = pz = pw = 0.f;
            }
            px += yx; py += yy; pz += yz; pw += yw;
        }
        s0 += yx; s1 += yy; s2 += yz; s3 += yw;
        q0 += yx * yx; q1 += yy * yy; q2 += yz * yz; q3 += yw * yw;
    }
    if (LAST && curg >= 0) {
        float* p = &g_pool[curg * HH + lane * 4];
        atomicAdd(p + 0, px); atomicAdd(p + 1, py);
        atomicAdd(p + 2, pz); atomicAdd(p + 3, pw);
    }
    __shared__ float red[2 * HH];
    red[tid] = 0.f;
    __syncthreads();
    atomicAdd(&red[lane * 4 + 0], s0);
    atomicAdd(&red[lane * 4 + 1], s1);
    atomicAdd(&red[lane * 4 + 2], s2);
    atomicAdd(&red[lane * 4 + 3], s3);
    atomicAdd(&red[HH + lane * 4 + 0], q0);
    atomicAdd(&red[HH + lane * 4 + 1], q1);
    atomicAdd(&red[HH + lane * 4 + 2], q2);
    atomicAdd(&red[HH + lane * 4 + 3], q3);
    __syncthreads();
    atomicAdd(&g_stats[tid], red[tid]);
    __threadfence();
    __syncthreads();
    __shared__ int isLast;
    if (tid == 0)
        isLast = (atomicAdd(&g_arr, 1u) == (unsigned)(AGG_BLOCKS - 1)) ? 1 : 0;
    __syncthreads();
    if (isLast) {
        if (tid < HH) {
            float m = g_stats[tid] * (1.0f / NN);
            float v = g_stats[HH + tid] * (1.0f / NN) - m * m;
            v = fmaxf(v, 0.f);
            float s = gamma[tid] * rsqrtf(v + 1e-5f);
            g_bns[tid] = s;
            g_bnt[tid] = beta[tid] - m * s;
            g_stats[tid] = 0.f;
            g_stats[HH + tid] = 0.f;
        }
        if (tid == 0) g_arr = 0u;
    }
}

// ---------------- final head ----------------
__device__ __forceinline__ int lb_batch(const void* batch, int val) {
    int lo = 0, hi = NN;
    while (lo < hi) {
        int mid = (lo + hi) >> 1;
        if ((int)idx_at(batch, mid) < val) lo = mid + 1;
        else hi = mid;
    }
    return lo;
}

__global__ void k_final(const void* __restrict__ batch,
                        const float* __restrict__ clinical,
                        const float* __restrict__ Wc,
                        const float* __restrict__ bc,
                        float* __restrict__ out) {
    int g = blockIdx.x, j = threadIdx.x;   // 128 threads
    __shared__ float cnt_s;
    if (j == 0) {
        int c = lb_batch(batch, g + 1) - lb_batch(batch, g);
        cnt_s = fmaxf((float)c, 1.0f);
    }
    __syncthreads();
    float p = g_pool[g * HH + j] / cnt_s;
    p = fmaf(p, g_bns[j], g_bnt[j]);
    float r0 = p * Wc[j * KK + 0];
    float r1 = p * Wc[j * KK + 1];
    if (j < CC) {
        float cl = clinical[g * CC + j];
        r0 = fmaf(cl, Wc[(HH + j) * KK + 0], r0);
        r1 = fmaf(cl, Wc[(HH + j) * KK + 1], r1);
    }
    __shared__ float sm0[128], sm1[128];
    sm0[j] = r0; sm1[j] = r1;
    __syncthreads();
    for (int d = 64; d > 0; d >>= 1) {
        if (j < d) { sm0[j] += sm0[j + d]; sm1[j] += sm1[j + d]; }
        __syncthreads();
    }
    if (j == 0) {
        out[g * KK + 0] = sm0[0] + bc[0];
        out[g * KK + 1] = sm1[0] + bc[1];
    }
}

// ---------------- launch ----------------
extern "C" void kernel_launch(void* const* d_in, const int* in_sizes, int n_in,
                              void* d_out, int out_size) {
    const float* x        = (const float*)d_in[0];
    const void*  ei       = d_in[1];
    const void*  batch    = d_in[2];
    const float* clinical = (const float*)d_in[3];
    const float* W1 = (const float*)d_in[4];  const float* b1 = (const float*)d_in[5];
    const float* W2 = (const float*)d_in[6];  const float* b2 = (const float*)d_in[7];
    const float* W3 = (const float*)d_in[8];  const float* b3 = (const float*)d_in[9];
    const float* g1 = (const float*)d_in[10]; const float* be1 = (const float*)d_in[11];
    const float* g2 = (const float*)d_in[12]; const float* be2 = (const float*)d_in[13];
    const float* g3 = (const float*)d_in[14]; const float* be3 = (const float*)d_in[15];
    const float* Wc = (const float*)d_in[16]; const float* bc = (const float*)d_in[17];
    float* out = (float*)d_out;

    const int gemm_blocks = (NN + 127) / 128;   // 782
    const int e_blocks    = (EE + 255) / 256;   // 6250
    const int n_blocks    = (NN + 255) / 256;   // 391
    const size_t smem0 = SMEM0_U32 * sizeof(uint32_t);   // 40 KB
    const size_t smem1 = SMEM1_U32 * sizeof(uint32_t);   // 60 KB

    cudaFuncSetAttribute(k_gemm_tc<0>,
                         cudaFuncAttributeMaxDynamicSharedMemorySize, (int)smem0);
    cudaFuncSetAttribute(k_gemm_tc<1>,
                         cudaFuncAttributeMaxDynamicSharedMemorySize, (int)smem1);

    k_init<<<n_blocks, 256>>>((const int*)ei);
    k_hist<<<e_blocks, 256>>>(ei);
    k_scan1<<<SCAN_BLOCKS, 256>>>();
    k_scan3<<<SCAN_BLOCKS, 256>>>();
    k_place<<<e_blocks, 256>>>(ei);

    // layer 1
    k_prepw1<<<64, 256>>>(W1);
    k_gemm_tc<0><<<gemm_blocks, 256, smem0>>>(x);
    k_agg<false><<<AGG_BLOCKS, 256>>>(b1, batch, g1, be1);

    // layer 2
    k_prepw_aff_r<<<65, 256>>>(W2);
    k_gemm_tc<1><<<gemm_blocks, 256, smem1>>>(nullptr);
    k_agg<false><<<AGG_BLOCKS, 256>>>(b2, batch, g2, be2);

    // layer 3
    k_prepw_aff_r<<<65, 256>>>(W3);
    k_gemm_tc<1><<<gemm_blocks, 256, smem1>>>(nullptr);
    k_agg<true><<<AGG_BLOCKS, 256>>>(b3, batch, g3, be3);

    k_final<<<GG, 128>>>(batch, clinical, Wc, bc, out);
}